// round 5
// baseline (speedup 1.0000x reference)
#include <cuda_runtime.h>
#include <cuda_bf16.h>
#include <cstdint>

#define NMAX 100000
#define DIM 128

// ---------------------------------------------------------------------------
// Scratch (__device__ globals per allocation-free rule)
// ---------------------------------------------------------------------------
__device__ __align__(16) float g_agg_in[(size_t)NMAX * DIM];
__device__ __align__(16) float g_agg_out[(size_t)NMAX * DIM];
__device__ float g_deg_in[NMAX];
__device__ float g_deg_out[NMAX];
// Weights, bf16 split, TRANSPOSED to [chunk][n][k]  (B[n][k] = W[k][n])
__device__ __align__(16) __nv_bfloat16 g_Bhi[3 * 128 * 128];
__device__ __align__(16) __nv_bfloat16 g_Blo[3 * 128 * 128];

// ---------------------------------------------------------------------------
// helpers
// ---------------------------------------------------------------------------
__device__ __forceinline__ void red_add_v4(float* p, float4 v) {
    asm volatile("red.global.add.v4.f32 [%0], {%1,%2,%3,%4};"
                 :: "l"(p), "f"(v.x), "f"(v.y), "f"(v.z), "f"(v.w)
                 : "memory");
}

__device__ __forceinline__ int clamp_idx(int v, int n) {
    return v < 0 ? 0 : (v >= n ? n - 1 : v);
}

__device__ __forceinline__ uint32_t smem_u32(const void* p) {
    uint32_t a;
    asm("{ .reg .u64 t; cvta.to.shared.u64 t, %1; cvt.u32.u64 %0, t; }"
        : "=r"(a) : "l"(p));
    return a;
}

__device__ __forceinline__ void ldsm_x4(uint32_t* r, uint32_t addr) {
    asm volatile("ldmatrix.sync.aligned.m8n8.x4.shared.b16 {%0,%1,%2,%3}, [%4];"
                 : "=r"(r[0]), "=r"(r[1]), "=r"(r[2]), "=r"(r[3]) : "r"(addr));
}

__device__ __forceinline__ void mma_bf16(float* d, const uint32_t* a,
                                         uint32_t b0, uint32_t b1) {
    asm volatile(
        "mma.sync.aligned.m16n8k16.row.col.f32.bf16.bf16.f32 "
        "{%0,%1,%2,%3}, {%4,%5,%6,%7}, {%8,%9}, {%0,%1,%2,%3};"
        : "+f"(d[0]), "+f"(d[1]), "+f"(d[2]), "+f"(d[3])
        : "r"(a[0]), "r"(a[1]), "r"(a[2]), "r"(a[3]), "r"(b0), "r"(b1));
}

// ---------------------------------------------------------------------------
// Zero accumulators + degree counters
// ---------------------------------------------------------------------------
__global__ void zero_kernel(int n) {
    const float4 z = make_float4(0.f, 0.f, 0.f, 0.f);
    int total4 = n * (DIM / 4);
    int stride = gridDim.x * blockDim.x;
    for (int i = blockIdx.x * blockDim.x + threadIdx.x; i < total4; i += stride) {
        reinterpret_cast<float4*>(g_agg_in)[i]  = z;
        reinterpret_cast<float4*>(g_agg_out)[i] = z;
    }
    for (int i = blockIdx.x * blockDim.x + threadIdx.x; i < n; i += stride) {
        g_deg_in[i]  = 0.f;
        g_deg_out[i] = 0.f;
    }
}

// ---------------------------------------------------------------------------
// Weight prep: split fp32 W[k][n] -> bf16 hi/lo, transposed to [n][k]
// ---------------------------------------------------------------------------
__global__ void prep_weights(const float* __restrict__ Wself,
                             const float* __restrict__ Ws2d,
                             const float* __restrict__ Wd2s) {
    int idx = blockIdx.x * blockDim.x + threadIdx.x;
    if (idx >= 3 * 16384) return;
    int chunk = idx >> 14;
    int rem   = idx & 16383;
    int k  = rem >> 7;
    int nn = rem & 127;
    const float* W = (chunk == 0) ? Wself : (chunk == 1) ? Ws2d : Wd2s;
    float w = __ldg(&W[k * 128 + nn]);
    __nv_bfloat16 hi = __float2bfloat16(w);
    float lo = w - __bfloat162float(hi);
    g_Bhi[chunk * 16384 + nn * 128 + k] = hi;
    g_Blo[chunk * 16384 + nn * 128 + k] = __float2bfloat16(lo);
}

// ---------------------------------------------------------------------------
// Scatter pass over a 64-column slice: one warp per edge, both directions.
// lanes 0-15: x[src] cols -> agg_in[dst];  lanes 16-31: x[dst] -> agg_out[src]
// Working set per pass: x-half 25.6MB + agg halves 51.2MB -> L2-resident.
// Pass 0 also counts degrees (lane 0 / lane 16).
// ---------------------------------------------------------------------------
template<int PASS>
__global__ void __launch_bounds__(256)
scatter_pass_kernel(const float* __restrict__ x,
                    const int* __restrict__ ei, int E, int n) {
    int warp = (blockIdx.x * blockDim.x + threadIdx.x) >> 5;
    int lane = threadIdx.x & 31;
    if (warp >= E) return;
    int src = clamp_idx(__ldg(&ei[warp]), n);
    int dst = clamp_idx(__ldg(&ei[E + warp]), n);

    const int col = PASS * 64 + (lane & 15) * 4;
    if (lane < 16) {
        float4 v = *reinterpret_cast<const float4*>(x + (size_t)src * DIM + col);
        red_add_v4(g_agg_in + (size_t)dst * DIM + col, v);
        if (PASS == 0 && lane == 0)
            atomicAdd(&g_deg_in[dst], 1.f);
    } else {
        float4 v = *reinterpret_cast<const float4*>(x + (size_t)dst * DIM + col);
        red_add_v4(g_agg_out + (size_t)src * DIM + col, v);
        if (PASS == 0 && lane == 16)
            atomicAdd(&g_deg_out[src], 1.f);
    }
}

// ---------------------------------------------------------------------------
// Tensor-core GEMM via mma.sync (bf16 3-term split), occupancy 2:
//   out[N,128] = [x | s_in*agg_in | s_out*agg_out] (N x 384) @ W (384x128) + b
// BM=128, BN=128; 8 warps; warp tile 32x64.
// K processed in 6 sub-steps of 64 (3 chunks x 2 halves); smem tiles
// 128 rows x 64 bf16 (144B padded stride) -> 72KB/CTA -> 2 CTAs/SM.
// ---------------------------------------------------------------------------
#define TSTRIDE 144                  // bytes per padded row (64 bf16 + 16B pad)
#define TBYTES  (128 * TSTRIDE)      // 18432

__global__ void __launch_bounds__(256, 2)
gemm_mma_kernel(const float* __restrict__ x,
                const float* __restrict__ bself,
                const float* __restrict__ bs2d,
                const float* __restrict__ bd2s,
                float* __restrict__ out, int n) {
    extern __shared__ char smem[];
    char* pA_hi = smem;
    char* pA_lo = smem + TBYTES;
    char* pB_hi = smem + 2 * TBYTES;
    char* pB_lo = smem + 3 * TBYTES;
    const uint32_t sA_hi = smem_u32(pA_hi);
    const uint32_t sA_lo = sA_hi + TBYTES;
    const uint32_t sB_hi = sA_hi + 2 * TBYTES;
    const uint32_t sB_lo = sA_hi + 3 * TBYTES;

    const int tid  = threadIdx.x;
    const int lane = tid & 31;
    const int wid  = tid >> 5;
    const int block_row = blockIdx.x * 128;

    // warp tile: 32 rows x 64 cols
    const int m0 = (wid & 3) * 32;
    const int n0 = (wid >> 2) * 64;

    // fill-thread mapping: 2 threads per row, each handles a 32-col quarter
    const int frow = tid >> 1;
    const int half = tid & 1;
    const int grow = min(block_row + frow, n - 1);

    // per-row scales for agg chunks (computed from degree, no scale kernel)
    const float s_in  = 0.5f / fmaxf(g_deg_in[grow],  1.f);
    const float s_out = 0.5f / fmaxf(g_deg_out[grow], 1.f);

    // ldmatrix per-lane base offsets (bytes)
    const uint32_t offA = (uint32_t)(m0 + (lane & 15)) * TSTRIDE + ((lane >> 4) << 4);
    const uint32_t offB = (uint32_t)(n0 + ((lane >> 4) << 3) + (lane & 7)) * TSTRIDE
                        + (((lane >> 3) & 1) << 4);

    float acc[2][8][4];
#pragma unroll
    for (int m = 0; m < 2; m++)
#pragma unroll
        for (int f = 0; f < 8; f++)
#pragma unroll
            for (int r = 0; r < 4; r++) acc[m][f][r] = 0.f;

#pragma unroll 1
    for (int step = 0; step < 6; step++) {
        const int chunk = step >> 1;       // 0..2
        const int kh    = step & 1;        // which 64-k half of the chunk

        // ---- A tile fill: 32 fp32 per thread, scale, split, store hi/lo bf16
        const float* Abase = (chunk == 0) ? x
                           : (chunk == 1) ? g_agg_in : g_agg_out;
        const float s = (chunk == 0) ? 1.0f : (chunk == 1) ? s_in : s_out;

        const float4* arow = reinterpret_cast<const float4*>(
            Abase + (size_t)grow * DIM + kh * 64 + half * 32);
        char* dst_hi = pA_hi + frow * TSTRIDE + half * 64;
        char* dst_lo = pA_lo + frow * TSTRIDE + half * 64;
#pragma unroll
        for (int j = 0; j < 8; j++) {
            float4 v = __ldg(&arow[j]);
            v.x *= s; v.y *= s; v.z *= s; v.w *= s;
            __nv_bfloat16 hx = __float2bfloat16(v.x);
            __nv_bfloat16 hy = __float2bfloat16(v.y);
            __nv_bfloat16 hz = __float2bfloat16(v.z);
            __nv_bfloat16 hw = __float2bfloat16(v.w);
            __nv_bfloat162 h01; h01.x = hx; h01.y = hy;
            __nv_bfloat162 h23; h23.x = hz; h23.y = hw;
            __nv_bfloat162 l01;
            l01.x = __float2bfloat16(v.x - __bfloat162float(hx));
            l01.y = __float2bfloat16(v.y - __bfloat162float(hy));
            __nv_bfloat162 l23;
            l23.x = __float2bfloat16(v.z - __bfloat162float(hz));
            l23.y = __float2bfloat16(v.w - __bfloat162float(hw));
            *reinterpret_cast<uint2*>(dst_hi + j * 8) =
                make_uint2(*reinterpret_cast<uint32_t*>(&h01),
                           *reinterpret_cast<uint32_t*>(&h23));
            *reinterpret_cast<uint2*>(dst_lo + j * 8) =
                make_uint2(*reinterpret_cast<uint32_t*>(&l01),
                           *reinterpret_cast<uint32_t*>(&l23));
        }

        // ---- B tile fill: copy pre-split bf16 weights (32 bf16 per thread)
        {
            const uint4* bh = reinterpret_cast<const uint4*>(
                g_Bhi + chunk * 16384 + frow * 128 + kh * 64 + half * 32);
            const uint4* bl = reinterpret_cast<const uint4*>(
                g_Blo + chunk * 16384 + frow * 128 + kh * 64 + half * 32);
            char* db_hi = pB_hi + frow * TSTRIDE + half * 64;
            char* db_lo = pB_lo + frow * TSTRIDE + half * 64;
#pragma unroll
            for (int j = 0; j < 4; j++) {
                *reinterpret_cast<uint4*>(db_hi + j * 16) = __ldg(&bh[j]);
                *reinterpret_cast<uint4*>(db_lo + j * 16) = __ldg(&bl[j]);
            }
        }

        __syncthreads();

        // ---- MMA: 4 k16-steps
#pragma unroll
        for (int ks = 0; ks < 4; ks++) {
            const uint32_t kb = (uint32_t)ks * 32;   // k16 * 2 bytes

            uint32_t ah[2][4], al[2][4];
#pragma unroll
            for (int m = 0; m < 2; m++) {
                uint32_t a = offA + (uint32_t)m * 16 * TSTRIDE + kb;
                ldsm_x4(ah[m], sA_hi + a);
                ldsm_x4(al[m], sA_lo + a);
            }
#pragma unroll
            for (int g = 0; g < 4; g++) {            // n16 groups
                uint32_t b = offB + (uint32_t)g * 16 * TSTRIDE + kb;
                uint32_t bh[4], bl[4];
                ldsm_x4(bh, sB_hi + b);
                ldsm_x4(bl, sB_lo + b);
#pragma unroll
                for (int m = 0; m < 2; m++) {
                    mma_bf16(acc[m][2 * g + 0], ah[m], bh[0], bh[1]);
                    mma_bf16(acc[m][2 * g + 1], ah[m], bh[2], bh[3]);
                    mma_bf16(acc[m][2 * g + 0], ah[m], bl[0], bl[1]);
                    mma_bf16(acc[m][2 * g + 1], ah[m], bl[2], bl[3]);
                    mma_bf16(acc[m][2 * g + 0], al[m], bh[0], bh[1]);
                    mma_bf16(acc[m][2 * g + 1], al[m], bh[2], bh[3]);
                }
            }
        }

        __syncthreads();
    }

    // ---- Epilogue: fused bias = b_self + 0.5*(b_s2d + b_d2s)
    const int colq = (lane & 3) * 2;       // 0,2,4,6
    const int rowq = lane >> 2;            // 0..7
#pragma unroll
    for (int f = 0; f < 8; f++) {
        int col = n0 + f * 8 + colq;
        float b0 = __ldg(&bself[col])     + 0.5f * (__ldg(&bs2d[col])     + __ldg(&bd2s[col]));
        float b1 = __ldg(&bself[col + 1]) + 0.5f * (__ldg(&bs2d[col + 1]) + __ldg(&bd2s[col + 1]));
#pragma unroll
        for (int m = 0; m < 2; m++) {
            int r0 = block_row + m0 + m * 16 + rowq;
#pragma unroll
            for (int h = 0; h < 2; h++) {       // d0d1 (row), d2d3 (row+8)
                int row = r0 + h * 8;
                if (row < n) {
                    float2 v = make_float2(acc[m][f][2 * h] + b0,
                                           acc[m][f][2 * h + 1] + b1);
                    *reinterpret_cast<float2*>(out + (size_t)row * DIM + col) = v;
                }
            }
        }
    }
}

// ---------------------------------------------------------------------------
// Launch
// ---------------------------------------------------------------------------
extern "C" void kernel_launch(void* const* d_in, const int* in_sizes, int n_in,
                              void* d_out, int out_size) {
    const float* x     = (const float*)d_in[0];
    const float* Wself = (const float*)d_in[1];
    const float* bself = (const float*)d_in[2];
    const float* Ws2d  = (const float*)d_in[3];
    const float* bs2d  = (const float*)d_in[4];
    const float* Wd2s  = (const float*)d_in[5];
    const float* bd2s  = (const float*)d_in[6];
    const int*   ei    = (const int*)d_in[7];

    int N = in_sizes[0] / DIM;      // 100000
    int E = in_sizes[7] / 2;        // 800000
    float* out = (float*)d_out;

    const int smem_bytes = 4 * TBYTES;   // 73728
    cudaFuncSetAttribute(gemm_mma_kernel,
                         cudaFuncAttributeMaxDynamicSharedMemorySize, smem_bytes);

    zero_kernel<<<2048, 256>>>(N);
    prep_weights<<<(3 * 16384 + 255) / 256, 256>>>(Wself, Ws2d, Wd2s);

    int scatter_blocks = (E * 32 + 255) / 256;
    scatter_pass_kernel<0><<<scatter_blocks, 256>>>(x, ei, E, N);
    scatter_pass_kernel<1><<<scatter_blocks, 256>>>(x, ei, E, N);

    gemm_mma_kernel<<<(N + 127) / 128, 256, smem_bytes>>>(x, bself, bs2d, bd2s,
                                                          out, N);
}

// round 6
// speedup vs baseline: 1.4358x; 1.4358x over previous
#include <cuda_runtime.h>
#include <cuda_bf16.h>
#include <cstdint>

#define NMAX 100000
#define DIM 128

// ---------------------------------------------------------------------------
// Scratch (__device__ globals per allocation-free rule)
// ---------------------------------------------------------------------------
__device__ __align__(16) float g_agg_in[(size_t)NMAX * DIM];
__device__ __align__(16) float g_agg_out[(size_t)NMAX * DIM];
__device__ float g_deg_in[NMAX];
__device__ float g_deg_out[NMAX];
// Packed A operand: [N][384] bf16, hi and lo planes (scales folded in)
__device__ __align__(16) __nv_bfloat16 g_Ahi[(size_t)NMAX * 384];
__device__ __align__(16) __nv_bfloat16 g_Alo[(size_t)NMAX * 384];
// Weights, bf16 split, TRANSPOSED to [chunk][n][k]  (B[n][k] = W[k][n])
__device__ __align__(16) __nv_bfloat16 g_Bhi[3 * 128 * 128];
__device__ __align__(16) __nv_bfloat16 g_Blo[3 * 128 * 128];

// ---------------------------------------------------------------------------
// helpers
// ---------------------------------------------------------------------------
__device__ __forceinline__ void red_add_v4(float* p, float4 v) {
    asm volatile("red.global.add.v4.f32 [%0], {%1,%2,%3,%4};"
                 :: "l"(p), "f"(v.x), "f"(v.y), "f"(v.z), "f"(v.w)
                 : "memory");
}

__device__ __forceinline__ int clamp_idx(int v, int n) {
    return v < 0 ? 0 : (v >= n ? n - 1 : v);
}

__device__ __forceinline__ uint32_t smem_u32(const void* p) {
    uint32_t a;
    asm("{ .reg .u64 t; cvta.to.shared.u64 t, %1; cvt.u32.u64 %0, t; }"
        : "=r"(a) : "l"(p));
    return a;
}

__device__ __forceinline__ void cp_async16(uint32_t dst, const void* src) {
    asm volatile("cp.async.cg.shared.global [%0], [%1], 16;"
                 :: "r"(dst), "l"(src) : "memory");
}
__device__ __forceinline__ void cp_commit() {
    asm volatile("cp.async.commit_group;" ::: "memory");
}
__device__ __forceinline__ void cp_wait1() {
    asm volatile("cp.async.wait_group 1;" ::: "memory");
}

__device__ __forceinline__ void ldsm_x4(uint32_t* r, uint32_t addr) {
    asm volatile("ldmatrix.sync.aligned.m8n8.x4.shared.b16 {%0,%1,%2,%3}, [%4];"
                 : "=r"(r[0]), "=r"(r[1]), "=r"(r[2]), "=r"(r[3]) : "r"(addr));
}

__device__ __forceinline__ void mma_bf16(float* d, const uint32_t* a,
                                         uint32_t b0, uint32_t b1) {
    asm volatile(
        "mma.sync.aligned.m16n8k16.row.col.f32.bf16.bf16.f32 "
        "{%0,%1,%2,%3}, {%4,%5,%6,%7}, {%8,%9}, {%0,%1,%2,%3};"
        : "+f"(d[0]), "+f"(d[1]), "+f"(d[2]), "+f"(d[3])
        : "r"(a[0]), "r"(a[1]), "r"(a[2]), "r"(a[3]), "r"(b0), "r"(b1));
}

// ---------------------------------------------------------------------------
// Zero accumulators + degree counters
// ---------------------------------------------------------------------------
__global__ void zero_kernel(int n) {
    const float4 z = make_float4(0.f, 0.f, 0.f, 0.f);
    int total4 = n * (DIM / 4);
    int stride = gridDim.x * blockDim.x;
    for (int i = blockIdx.x * blockDim.x + threadIdx.x; i < total4; i += stride) {
        reinterpret_cast<float4*>(g_agg_in)[i]  = z;
        reinterpret_cast<float4*>(g_agg_out)[i] = z;
    }
    for (int i = blockIdx.x * blockDim.x + threadIdx.x; i < n; i += stride) {
        g_deg_in[i]  = 0.f;
        g_deg_out[i] = 0.f;
    }
}

// ---------------------------------------------------------------------------
// Weight prep: split fp32 W[k][n] -> bf16 hi/lo, transposed to [n][k]
// ---------------------------------------------------------------------------
__global__ void prep_weights(const float* __restrict__ Wself,
                             const float* __restrict__ Ws2d,
                             const float* __restrict__ Wd2s) {
    int idx = blockIdx.x * blockDim.x + threadIdx.x;
    if (idx >= 3 * 16384) return;
    int chunk = idx >> 14;
    int rem   = idx & 16383;
    int k  = rem >> 7;
    int nn = rem & 127;
    const float* W = (chunk == 0) ? Wself : (chunk == 1) ? Ws2d : Wd2s;
    float w = __ldg(&W[k * 128 + nn]);
    __nv_bfloat16 hi = __float2bfloat16(w);
    float lo = w - __bfloat162float(hi);
    g_Bhi[chunk * 16384 + nn * 128 + k] = hi;
    g_Blo[chunk * 16384 + nn * 128 + k] = __float2bfloat16(lo);
}

// ---------------------------------------------------------------------------
// Scatter: one warp per edge, both directions, v4 atomics (R4 form),
// with degree counting fused (lane 0: in, lane 16: out).
// ---------------------------------------------------------------------------
__global__ void scatter_kernel(const float* __restrict__ x,
                               const int* __restrict__ ei, int E, int n) {
    int warp = (blockIdx.x * blockDim.x + threadIdx.x) >> 5;
    int lane = threadIdx.x & 31;
    if (warp >= E) return;
    int src = clamp_idx(__ldg(&ei[warp]), n);
    int dst = clamp_idx(__ldg(&ei[E + warp]), n);

    float4 vs = reinterpret_cast<const float4*>(x + (size_t)src * DIM)[lane];
    red_add_v4(g_agg_in + (size_t)dst * DIM + lane * 4, vs);

    float4 vd = reinterpret_cast<const float4*>(x + (size_t)dst * DIM)[lane];
    red_add_v4(g_agg_out + (size_t)src * DIM + lane * 4, vd);

    if (lane == 0)  atomicAdd(&g_deg_in[dst],  1.f);
    if (lane == 16) atomicAdd(&g_deg_out[src], 1.f);
}

// ---------------------------------------------------------------------------
// Pack A: [x | s_in*agg_in | s_out*agg_out] -> bf16 hi/lo planes [N][384].
// One warp per node; scales folded in here.
// ---------------------------------------------------------------------------
__global__ void __launch_bounds__(256)
pack_A_kernel(const float* __restrict__ x, int n) {
    int node = (blockIdx.x * blockDim.x + threadIdx.x) >> 5;
    int lane = threadIdx.x & 31;
    if (node >= n) return;

    const float s_in  = 0.5f / fmaxf(g_deg_in[node],  1.f);
    const float s_out = 0.5f / fmaxf(g_deg_out[node], 1.f);

#pragma unroll
    for (int chunk = 0; chunk < 3; chunk++) {
        const float* src = (chunk == 0) ? x
                         : (chunk == 1) ? g_agg_in : g_agg_out;
        const float s = (chunk == 0) ? 1.0f : (chunk == 1) ? s_in : s_out;

        float4 v = reinterpret_cast<const float4*>(src + (size_t)node * DIM)[lane];
        v.x *= s; v.y *= s; v.z *= s; v.w *= s;

        __nv_bfloat16 hx = __float2bfloat16(v.x);
        __nv_bfloat16 hy = __float2bfloat16(v.y);
        __nv_bfloat16 hz = __float2bfloat16(v.z);
        __nv_bfloat16 hw = __float2bfloat16(v.w);
        __nv_bfloat162 h01; h01.x = hx; h01.y = hy;
        __nv_bfloat162 h23; h23.x = hz; h23.y = hw;
        __nv_bfloat162 l01;
        l01.x = __float2bfloat16(v.x - __bfloat162float(hx));
        l01.y = __float2bfloat16(v.y - __bfloat162float(hy));
        __nv_bfloat162 l23;
        l23.x = __float2bfloat16(v.z - __bfloat162float(hz));
        l23.y = __float2bfloat16(v.w - __bfloat162float(hw));

        size_t off = (size_t)node * 384 + chunk * 128 + lane * 4;
        *reinterpret_cast<uint2*>(g_Ahi + off) =
            make_uint2(*reinterpret_cast<uint32_t*>(&h01),
                       *reinterpret_cast<uint32_t*>(&h23));
        *reinterpret_cast<uint2*>(g_Alo + off) =
            make_uint2(*reinterpret_cast<uint32_t*>(&l01),
                       *reinterpret_cast<uint32_t*>(&l23));
    }
}

// ---------------------------------------------------------------------------
// Pure-bf16 GEMM with cp.async 2-stage pipeline:
//   out[N,128] = A[N,384] @ W(384x128) + bias, 3-term split hi/lo.
// BM=128, BN=128, BK=64 (6 steps); 8 warps, warp tile 32x64.
// Stage = A_hi|A_lo|B_hi|B_lo planes of 128 rows x 144B  -> 72KB; x2 = 144KB.
// ---------------------------------------------------------------------------
#define TSTRIDE 144
#define PLANE   (128 * TSTRIDE)      // 18432
#define STAGE   (4 * PLANE)          // 73728

__global__ void __launch_bounds__(256, 1)
gemm_mma_kernel(const float* __restrict__ bself,
                const float* __restrict__ bs2d,
                const float* __restrict__ bd2s,
                float* __restrict__ out, int n) {
    extern __shared__ char smem[];
    const uint32_t sbase = smem_u32(smem);

    const int tid  = threadIdx.x;
    const int lane = tid & 31;
    const int wid  = tid >> 5;
    const int block_row = blockIdx.x * 128;

    // warp tile: 32 rows x 64 cols
    const int m0 = (wid & 3) * 32;
    const int n0 = (wid >> 2) * 64;

    // fill mapping: 2 threads per row, each 64B (4 x 16B)
    const int frow = tid >> 1;
    const int half = tid & 1;
    const int grow = min(block_row + frow, n - 1);

    // per-step fill: issue cp.asyncs for step s into stage buffer st
    auto issue_stage = [&](int s, int st) {
        const uint32_t buf = sbase + st * STAGE;
        const uint32_t d   = (uint32_t)frow * TSTRIDE + half * 64;
        const int chunk = s >> 1;
        const int kh    = s & 1;
        // A planes: contiguous 128B at row*384 + s*64
        const char* srcAh = (const char*)(g_Ahi + (size_t)grow * 384 + s * 64)
                          + half * 64;
        const char* srcAl = (const char*)(g_Alo + (size_t)grow * 384 + s * 64)
                          + half * 64;
        // B planes: row frow is n index
        const char* srcBh = (const char*)(g_Bhi + chunk * 16384 + frow * 128 + kh * 64)
                          + half * 64;
        const char* srcBl = (const char*)(g_Blo + chunk * 16384 + frow * 128 + kh * 64)
                          + half * 64;
#pragma unroll
        for (int j = 0; j < 4; j++) {
            cp_async16(buf + 0 * PLANE + d + j * 16, srcAh + j * 16);
            cp_async16(buf + 1 * PLANE + d + j * 16, srcAl + j * 16);
            cp_async16(buf + 2 * PLANE + d + j * 16, srcBh + j * 16);
            cp_async16(buf + 3 * PLANE + d + j * 16, srcBl + j * 16);
        }
    };

    // ldmatrix per-lane base offsets (bytes within a plane)
    const uint32_t offA = (uint32_t)(m0 + (lane & 15)) * TSTRIDE + ((lane >> 4) << 4);
    const uint32_t offB = (uint32_t)(n0 + ((lane >> 4) << 3) + (lane & 7)) * TSTRIDE
                        + (((lane >> 3) & 1) << 4);

    float acc[2][8][4];
#pragma unroll
    for (int m = 0; m < 2; m++)
#pragma unroll
        for (int f = 0; f < 8; f++)
#pragma unroll
            for (int r = 0; r < 4; r++) acc[m][f][r] = 0.f;

    // prologue: stages 0 and 1
    issue_stage(0, 0); cp_commit();
    issue_stage(1, 1); cp_commit();

#pragma unroll 1
    for (int s = 0; s < 6; s++) {
        cp_wait1();            // stage s landed
        __syncthreads();

        const uint32_t buf  = sbase + (s & 1) * STAGE;
        const uint32_t aHi = buf + 0 * PLANE, aLo = buf + 1 * PLANE;
        const uint32_t bHi = buf + 2 * PLANE, bLo = buf + 3 * PLANE;

#pragma unroll
        for (int ks = 0; ks < 4; ks++) {
            const uint32_t kb = (uint32_t)ks * 32;

            uint32_t ah[2][4], al[2][4];
#pragma unroll
            for (int m = 0; m < 2; m++) {
                uint32_t a = offA + (uint32_t)m * 16 * TSTRIDE + kb;
                ldsm_x4(ah[m], aHi + a);
                ldsm_x4(al[m], aLo + a);
            }
#pragma unroll
            for (int g = 0; g < 4; g++) {
                uint32_t b = offB + (uint32_t)g * 16 * TSTRIDE + kb;
                uint32_t bh[4], bl[4];
                ldsm_x4(bh, bHi + b);
                ldsm_x4(bl, bLo + b);
#pragma unroll
                for (int m = 0; m < 2; m++) {
                    mma_bf16(acc[m][2 * g + 0], ah[m], bh[0], bh[1]);
                    mma_bf16(acc[m][2 * g + 1], ah[m], bh[2], bh[3]);
                    mma_bf16(acc[m][2 * g + 0], ah[m], bl[0], bl[1]);
                    mma_bf16(acc[m][2 * g + 1], ah[m], bl[2], bl[3]);
                    mma_bf16(acc[m][2 * g + 0], al[m], bh[0], bh[1]);
                    mma_bf16(acc[m][2 * g + 1], al[m], bh[2], bh[3]);
                }
            }
        }

        __syncthreads();       // all warps done reading stage s
        if (s + 2 < 6) issue_stage(s + 2, s & 1);
        cp_commit();           // keep group accounting uniform
    }

    // ---- Epilogue: fused bias = b_self + 0.5*(b_s2d + b_d2s)
    const int colq = (lane & 3) * 2;
    const int rowq = lane >> 2;
#pragma unroll
    for (int f = 0; f < 8; f++) {
        int col = n0 + f * 8 + colq;
        float b0 = __ldg(&bself[col])     + 0.5f * (__ldg(&bs2d[col])     + __ldg(&bd2s[col]));
        float b1 = __ldg(&bself[col + 1]) + 0.5f * (__ldg(&bs2d[col + 1]) + __ldg(&bd2s[col + 1]));
#pragma unroll
        for (int m = 0; m < 2; m++) {
            int r0 = block_row + m0 + m * 16 + rowq;
#pragma unroll
            for (int h = 0; h < 2; h++) {
                int row = r0 + h * 8;
                if (row < n) {
                    float2 v = make_float2(acc[m][f][2 * h] + b0,
                                           acc[m][f][2 * h + 1] + b1);
                    *reinterpret_cast<float2*>(out + (size_t)row * DIM + col) = v;
                }
            }
        }
    }
}

// ---------------------------------------------------------------------------
// Launch
// ---------------------------------------------------------------------------
extern "C" void kernel_launch(void* const* d_in, const int* in_sizes, int n_in,
                              void* d_out, int out_size) {
    const float* x     = (const float*)d_in[0];
    const float* Wself = (const float*)d_in[1];
    const float* bself = (const float*)d_in[2];
    const float* Ws2d  = (const float*)d_in[3];
    const float* bs2d  = (const float*)d_in[4];
    const float* Wd2s  = (const float*)d_in[5];
    const float* bd2s  = (const float*)d_in[6];
    const int*   ei    = (const int*)d_in[7];

    int N = in_sizes[0] / DIM;      // 100000
    int E = in_sizes[7] / 2;        // 800000
    float* out = (float*)d_out;

    const int smem_bytes = 2 * STAGE;   // 147456
    cudaFuncSetAttribute(gemm_mma_kernel,
                         cudaFuncAttributeMaxDynamicSharedMemorySize, smem_bytes);

    zero_kernel<<<2048, 256>>>(N);
    prep_weights<<<(3 * 16384 + 255) / 256, 256>>>(Wself, Ws2d, Wd2s);

    int scatter_blocks = (E * 32 + 255) / 256;
    scatter_kernel<<<scatter_blocks, 256>>>(x, ei, E, N);

    pack_A_kernel<<<(N * 32 + 255) / 256, 256>>>(x, N);

    gemm_mma_kernel<<<(N + 127) / 128, 256, smem_bytes>>>(bself, bs2d, bd2s,
                                                          out, N);
}